// round 4
// baseline (speedup 1.0000x reference)
#include <cuda_runtime.h>

// SSIM loss, fused single pass, separable box filter.
// Vertical sliding column-sums (5 quantities) live in SMEM; each thread
// produces 4 adjacent output columns per row via incremental horizontal sums.
// img1, img2: [32,1,1024,1024] fp32. window: uniform 11x11 (1/121), hardcoded.

#define IMG_H 1024
#define IMG_W 1024
#define BATCH 32
#define TPB 128
#define TILE_OUT 512              // output columns per block
#define GROUPS 132                // 4-col groups staged: cols [x0-8, x0+520)
#define CS_W (GROUPS * 4)         // 528
#define ROWS_PER_BLK 64
#define PADR 5

static __device__ double g_accum;

__global__ void zero_acc_kernel() { g_accum = 0.0; }

__global__ void finalize_kernel(float* out) {
    *out = (float)(1.0 - g_accum * (1.0 / 33554432.0));  // mean over 32*1024*1024
}

__global__ __launch_bounds__(TPB)
void ssim_kernel(const float* __restrict__ img1, const float* __restrict__ img2) {
    // Column sums over the current 11-row vertical window, 5 quantities.
    __shared__ __align__(16) float sm[5][CS_W];
    __shared__ float warpsum[TPB / 32];

    const int tx = threadIdx.x;
    const int x0 = blockIdx.x * TILE_OUT;
    const int y0 = blockIdx.y * ROWS_PER_BLK;
    const size_t base = (size_t)blockIdx.z * IMG_H * IMG_W;
    const float* __restrict__ p1 = img1 + base;
    const float* __restrict__ p2 = img2 + base;

    const float inv121 = 1.0f / 121.0f;
    const float C1v = 1e-4f;
    const float C2v = 9e-4f;

    // zero the column sums
    for (int i = tx; i < 5 * CS_W; i += TPB) ((float*)sm)[i] = 0.f;

    // float4 pair load with full OOB zeroing (groups are fully in or fully out of x-range)
    auto load_pair = [&](int row, int c0, float4& a, float4& b) {
        if (row >= 0 && row < IMG_H && c0 >= 0 && c0 + 3 < IMG_W) {
            const size_t idx = (size_t)row * IMG_W + c0;
            a = *(const float4*)(p1 + idx);
            b = *(const float4*)(p2 + idx);
        } else {
            a = make_float4(0.f, 0.f, 0.f, 0.f);
            b = make_float4(0.f, 0.f, 0.f, 0.f);
        }
    };

    // colsum[q][4g..4g+3] += contrib(row_new) - contrib(row_old)
    auto update_group = [&](int g, int row_new, int row_old) {
        const int c0 = x0 - 8 + 4 * g;
        float4 an, bn, ao, bo;
        load_pair(row_new, c0, an, bn);
        load_pair(row_old, c0, ao, bo);

        float4 v;
        v = *(float4*)&sm[0][4 * g];
        v.x += an.x - ao.x; v.y += an.y - ao.y; v.z += an.z - ao.z; v.w += an.w - ao.w;
        *(float4*)&sm[0][4 * g] = v;

        v = *(float4*)&sm[1][4 * g];
        v.x += bn.x - bo.x; v.y += bn.y - bo.y; v.z += bn.z - bo.z; v.w += bn.w - bo.w;
        *(float4*)&sm[1][4 * g] = v;

        v = *(float4*)&sm[2][4 * g];
        v.x += an.x * an.x - ao.x * ao.x; v.y += an.y * an.y - ao.y * ao.y;
        v.z += an.z * an.z - ao.z * ao.z; v.w += an.w * an.w - ao.w * ao.w;
        *(float4*)&sm[2][4 * g] = v;

        v = *(float4*)&sm[3][4 * g];
        v.x += bn.x * bn.x - bo.x * bo.x; v.y += bn.y * bn.y - bo.y * bo.y;
        v.z += bn.z * bn.z - bo.z * bo.z; v.w += bn.w * bn.w - bo.w * bo.w;
        *(float4*)&sm[3][4 * g] = v;

        v = *(float4*)&sm[4][4 * g];
        v.x += an.x * bn.x - ao.x * bo.x; v.y += an.y * bn.y - ao.y * bo.y;
        v.z += an.z * bn.z - ao.z * bo.z; v.w += an.w * bn.w - ao.w * bo.w;
        *(float4*)&sm[4][4 * g] = v;
    };

    auto ssim_val = [&](float s1, float s2, float s11, float s22, float s12) {
        float mu1 = s1 * inv121, mu2 = s2 * inv121;
        float e11 = s11 * inv121, e22 = s22 * inv121, e12 = s12 * inv121;
        float mu1s = mu1 * mu1, mu2s = mu2 * mu2, mu12 = mu1 * mu2;
        float num = (2.0f * mu12 + C1v) * (2.0f * (e12 - mu12) + C2v);
        float den = (mu1s + mu2s + C1v) * ((e11 - mu1s) + (e22 - mu2s) + C2v);
        return __fdividef(num, den);
    };

    __syncthreads();

    // ---- prologue: accumulate rows y0-5 .. y0+4 (old row forced OOB -> zero) ----
    #pragma unroll 1
    for (int j = 0; j < 10; j++) {
        const int rn = y0 - PADR + j;
        update_group(tx, rn, -1);
        if (tx < GROUPS - TPB) update_group(TPB + tx, rn, -1);
        __syncthreads();
    }

    float acc = 0.f;

    // ---- main loop over output rows ----
    #pragma unroll 1
    for (int i = 0; i < ROWS_PER_BLK; i++) {
        const int oy = y0 + i;
        // slide vertical window: add row oy+5, remove row oy-6.
        // At i==0 the window grows 10 -> 11 rows: row oy-6 was never added
        // (prologue covered y0-5..y0+4 only), so subtract nothing.
        const int ro = (i == 0) ? -1 : (oy - PADR - 1);
        update_group(tx, oy + PADR, ro);
        if (tx < GROUPS - TPB) update_group(TPB + tx, oy + PADR, ro);
        __syncthreads();

        // horizontal: 4 outputs at cs = 4*tx+8 .. 4*tx+11
        float w0[5], w1[5], w2[5], w3[5];
        #pragma unroll
        for (int q = 0; q < 5; q++) {
            const float* s = sm[q];
            float4 v0 = *(const float4*)&s[4 * tx];
            float4 a1 = *(const float4*)&s[4 * tx + 4];
            float4 a2 = *(const float4*)&s[4 * tx + 8];
            float4 a3 = *(const float4*)&s[4 * tx + 12];
            float  e  = s[4 * tx + 16];
            float base10 = a1.x + a1.y + a1.z + a1.w
                         + a2.x + a2.y + a2.z + a2.w
                         + a3.x + a3.y;               // cs 4t+4 .. 4t+13
            w0[q] = base10 + v0.w;                    // cs 4t+3 .. 4t+13
            w1[q] = base10 + a3.z;                    // cs 4t+4 .. 4t+14
            w2[q] = w1[q] - a1.x + a3.w;              // cs 4t+5 .. 4t+15
            w3[q] = w2[q] - a1.y + e;                 // cs 4t+6 .. 4t+16
        }
        acc += ssim_val(w0[0], w0[1], w0[2], w0[3], w0[4]);
        acc += ssim_val(w1[0], w1[1], w1[2], w1[3], w1[4]);
        acc += ssim_val(w2[0], w2[1], w2[2], w2[3], w2[4]);
        acc += ssim_val(w3[0], w3[1], w3[2], w3[3], w3[4]);

        __syncthreads();  // readers done before next row's RMW
    }

    // ---- block reduction, one double atomic per block ----
    #pragma unroll
    for (int off = 16; off > 0; off >>= 1)
        acc += __shfl_down_sync(0xffffffffu, acc, off);
    if ((tx & 31) == 0) warpsum[tx >> 5] = acc;
    __syncthreads();
    if (tx == 0) {
        float s = 0.f;
        #pragma unroll
        for (int w = 0; w < TPB / 32; w++) s += warpsum[w];
        atomicAdd(&g_accum, (double)s);
    }
}

extern "C" void kernel_launch(void* const* d_in, const int* in_sizes, int n_in,
                              void* d_out, int out_size) {
    const float* img1 = (const float*)d_in[0];
    const float* img2 = (const float*)d_in[1];
    (void)in_sizes; (void)n_in; (void)out_size;

    zero_acc_kernel<<<1, 1>>>();
    dim3 grid(IMG_W / TILE_OUT, IMG_H / ROWS_PER_BLK, BATCH);  // (2, 16, 32)
    ssim_kernel<<<grid, TPB>>>(img1, img2);
    finalize_kernel<<<1, 1>>>((float*)d_out);
}

// round 5
// speedup vs baseline: 1.0451x; 1.0451x over previous
#include <cuda_runtime.h>

// SSIM loss, fused single pass, separable box filter.
// Vertical sliding column-sums (5 quantities) live in SMEM; each thread
// produces 4 adjacent output columns per row via incremental horizontal sums.
// img1, img2: [32,1,1024,1024] fp32. window: uniform 11x11 (1/121), hardcoded.

#define IMG_H 1024
#define IMG_W 1024
#define BATCH 32
#define TPB 128
#define TILE_OUT 512              // output columns per block
#define GROUPS 132                // 4-col groups staged: cols [x0-8, x0+520)
#define CS_W (GROUPS * 4)         // 528
#define ROWS_PER_BLK 64
#define PADR 5

static __device__ double g_accum;

__global__ void zero_acc_kernel() { g_accum = 0.0; }

__global__ void finalize_kernel(float* out) {
    *out = (float)(1.0 - g_accum * (1.0 / 33554432.0));  // mean over 32*1024*1024
}

__global__ __launch_bounds__(TPB)
void ssim_kernel(const float* __restrict__ img1, const float* __restrict__ img2) {
    // Column sums over the current 11-row vertical window, 5 quantities.
    __shared__ __align__(16) float sm[5][CS_W];
    __shared__ float warpsum[TPB / 32];

    const int tx = threadIdx.x;
    const int x0 = blockIdx.x * TILE_OUT;
    const int y0 = blockIdx.y * ROWS_PER_BLK;
    const size_t base = (size_t)blockIdx.z * IMG_H * IMG_W;
    const float* __restrict__ p1 = img1 + base;
    const float* __restrict__ p2 = img2 + base;

    const float inv121 = 1.0f / 121.0f;
    const float C1v = 1e-4f;
    const float C2v = 9e-4f;

    // zero the column sums
    for (int i = tx; i < 5 * CS_W; i += TPB) ((float*)sm)[i] = 0.f;

    // float4 pair load with full OOB zeroing (groups are fully in or fully out of x-range)
    auto load_pair = [&](int row, int c0, float4& a, float4& b) {
        if (row >= 0 && row < IMG_H && c0 >= 0 && c0 + 3 < IMG_W) {
            const size_t idx = (size_t)row * IMG_W + c0;
            a = *(const float4*)(p1 + idx);
            b = *(const float4*)(p2 + idx);
        } else {
            a = make_float4(0.f, 0.f, 0.f, 0.f);
            b = make_float4(0.f, 0.f, 0.f, 0.f);
        }
    };

    // colsum[q][4g..4g+3] += contrib(row_new) - contrib(row_old)
    auto update_group = [&](int g, int row_new, int row_old) {
        const int c0 = x0 - 8 + 4 * g;
        float4 an, bn, ao, bo;
        load_pair(row_new, c0, an, bn);
        load_pair(row_old, c0, ao, bo);

        float4 v;
        v = *(float4*)&sm[0][4 * g];
        v.x += an.x - ao.x; v.y += an.y - ao.y; v.z += an.z - ao.z; v.w += an.w - ao.w;
        *(float4*)&sm[0][4 * g] = v;

        v = *(float4*)&sm[1][4 * g];
        v.x += bn.x - bo.x; v.y += bn.y - bo.y; v.z += bn.z - bo.z; v.w += bn.w - bo.w;
        *(float4*)&sm[1][4 * g] = v;

        v = *(float4*)&sm[2][4 * g];
        v.x += an.x * an.x - ao.x * ao.x; v.y += an.y * an.y - ao.y * ao.y;
        v.z += an.z * an.z - ao.z * ao.z; v.w += an.w * an.w - ao.w * ao.w;
        *(float4*)&sm[2][4 * g] = v;

        v = *(float4*)&sm[3][4 * g];
        v.x += bn.x * bn.x - bo.x * bo.x; v.y += bn.y * bn.y - bo.y * bo.y;
        v.z += bn.z * bn.z - bo.z * bo.z; v.w += bn.w * bn.w - bo.w * bo.w;
        *(float4*)&sm[3][4 * g] = v;

        v = *(float4*)&sm[4][4 * g];
        v.x += an.x * bn.x - ao.x * bo.x; v.y += an.y * bn.y - ao.y * bo.y;
        v.z += an.z * bn.z - ao.z * bo.z; v.w += an.w * bn.w - ao.w * bo.w;
        *(float4*)&sm[4][4 * g] = v;
    };

    auto ssim_val = [&](float s1, float s2, float s11, float s22, float s12) {
        float mu1 = s1 * inv121, mu2 = s2 * inv121;
        float e11 = s11 * inv121, e22 = s22 * inv121, e12 = s12 * inv121;
        float mu1s = mu1 * mu1, mu2s = mu2 * mu2, mu12 = mu1 * mu2;
        float num = (2.0f * mu12 + C1v) * (2.0f * (e12 - mu12) + C2v);
        float den = (mu1s + mu2s + C1v) * ((e11 - mu1s) + (e22 - mu2s) + C2v);
        return __fdividef(num, den);
    };

    __syncthreads();

    // ---- prologue: accumulate rows y0-5 .. y0+4 (old row forced OOB -> zero) ----
    #pragma unroll 1
    for (int j = 0; j < 10; j++) {
        const int rn = y0 - PADR + j;
        update_group(tx, rn, -1);
        if (tx < GROUPS - TPB) update_group(TPB + tx, rn, -1);
        __syncthreads();
    }

    float acc = 0.f;

    // ---- main loop over output rows ----
    #pragma unroll 1
    for (int i = 0; i < ROWS_PER_BLK; i++) {
        const int oy = y0 + i;
        // slide vertical window: add row oy+5, remove row oy-6.
        // At i==0 the window grows 10 -> 11 rows: row oy-6 was never added
        // (prologue covered y0-5..y0+4 only), so subtract nothing.
        const int ro = (i == 0) ? -1 : (oy - PADR - 1);
        update_group(tx, oy + PADR, ro);
        if (tx < GROUPS - TPB) update_group(TPB + tx, oy + PADR, ro);
        __syncthreads();

        // horizontal: 4 outputs at cs = 4*tx+8 .. 4*tx+11
        float w0[5], w1[5], w2[5], w3[5];
        #pragma unroll
        for (int q = 0; q < 5; q++) {
            const float* s = sm[q];
            float4 v0 = *(const float4*)&s[4 * tx];
            float4 a1 = *(const float4*)&s[4 * tx + 4];
            float4 a2 = *(const float4*)&s[4 * tx + 8];
            float4 a3 = *(const float4*)&s[4 * tx + 12];
            float  e  = s[4 * tx + 16];
            float base10 = a1.x + a1.y + a1.z + a1.w
                         + a2.x + a2.y + a2.z + a2.w
                         + a3.x + a3.y;               // cs 4t+4 .. 4t+13
            w0[q] = base10 + v0.w;                    // cs 4t+3 .. 4t+13
            w1[q] = base10 + a3.z;                    // cs 4t+4 .. 4t+14
            w2[q] = w1[q] - a1.x + a3.w;              // cs 4t+5 .. 4t+15
            w3[q] = w2[q] - a1.y + e;                 // cs 4t+6 .. 4t+16
        }
        acc += ssim_val(w0[0], w0[1], w0[2], w0[3], w0[4]);
        acc += ssim_val(w1[0], w1[1], w1[2], w1[3], w1[4]);
        acc += ssim_val(w2[0], w2[1], w2[2], w2[3], w2[4]);
        acc += ssim_val(w3[0], w3[1], w3[2], w3[3], w3[4]);

        __syncthreads();  // readers done before next row's RMW
    }

    // ---- block reduction, one double atomic per block ----
    #pragma unroll
    for (int off = 16; off > 0; off >>= 1)
        acc += __shfl_down_sync(0xffffffffu, acc, off);
    if ((tx & 31) == 0) warpsum[tx >> 5] = acc;
    __syncthreads();
    if (tx == 0) {
        float s = 0.f;
        #pragma unroll
        for (int w = 0; w < TPB / 32; w++) s += warpsum[w];
        atomicAdd(&g_accum, (double)s);
    }
}

extern "C" void kernel_launch(void* const* d_in, const int* in_sizes, int n_in,
                              void* d_out, int out_size) {
    const float* img1 = (const float*)d_in[0];
    const float* img2 = (const float*)d_in[1];
    (void)in_sizes; (void)n_in; (void)out_size;

    zero_acc_kernel<<<1, 1>>>();
    dim3 grid(IMG_W / TILE_OUT, IMG_H / ROWS_PER_BLK, BATCH);  // (2, 16, 32)
    ssim_kernel<<<grid, TPB>>>(img1, img2);
    finalize_kernel<<<1, 1>>>((float*)d_out);
}

// round 7
// speedup vs baseline: 1.5060x; 1.4410x over previous
#include <cuda_runtime.h>

// SSIM loss — fully register/shuffle-resident separable box filter.
// Each lane owns 8 columns of packed-f32x2 vertical column sums (5 quantities),
// slides the 11-row window down, builds 11-col horizontal sums via warp
// shuffles (lanes need only +-1 neighbors), computes rescaled SSIM with
// packed math. No shared memory, no barriers in the main loop.

#define IMG_H 1024
#define IMG_W 1024
#define BATCH 32
#define PADR 5
#define OUT_W 240          // output cols per warp strip (lanes 1..30 x 8)
#define NSTRIPS 5          // ceil(1024/240); strip 4 partial (64 cols)
#define YCHUNK 64
#define NYCH 16

typedef unsigned long long u64;

static __device__ double g_accum;

__global__ void zero_acc_kernel() { g_accum = 0.0; }

__global__ void finalize_kernel(float* out) {
    *out = (float)(1.0 - g_accum * (1.0 / 33554432.0));  // mean over 32*1024*1024
}

__device__ __forceinline__ u64 pk(float lo, float hi) {
    u64 r; asm("mov.b64 %0,{%1,%2};" : "=l"(r) : "f"(lo), "f"(hi)); return r;
}
__device__ __forceinline__ void upk(u64 v, float& lo, float& hi) {
    asm("mov.b64 {%0,%1},%2;" : "=f"(lo), "=f"(hi) : "l"(v));
}
__device__ __forceinline__ u64 f2add(u64 a, u64 b) {
    u64 r; asm("add.rn.f32x2 %0,%1,%2;" : "=l"(r) : "l"(a), "l"(b)); return r;
}
__device__ __forceinline__ u64 f2mul(u64 a, u64 b) {
    u64 r; asm("mul.rn.f32x2 %0,%1,%2;" : "=l"(r) : "l"(a), "l"(b)); return r;
}
__device__ __forceinline__ u64 f2fma(u64 a, u64 b, u64 c) {
    u64 r; asm("fma.rn.f32x2 %0,%1,%2,%3;" : "=l"(r) : "l"(a), "l"(b), "l"(c)); return r;
}

#define NEG1PK 0xBF800000BF800000ULL   // (-1.0f, -1.0f)

__global__ __launch_bounds__(32)
void ssim_kernel(const float* __restrict__ img1, const float* __restrict__ img2) {
    const int lane  = threadIdx.x;
    const int strip = blockIdx.x;
    const int y0    = blockIdx.y * YCHUNK;
    const size_t ib = (size_t)blockIdx.z * (IMG_H * IMG_W);
    const float* __restrict__ p1 = img1 + ib;
    const float* __restrict__ p2 = img2 + ib;

    const int j = strip * OUT_W - 8 + lane * 8;   // first owned column (may be OOB)
    const unsigned FULL = 0xffffffffu;
    const bool prod = (lane >= 1) && (lane <= 30);

    // packed column sums: quantities {a, b, a^2, b^2, ab} x 4 col-pairs
    u64 cs[5][4];
    #pragma unroll
    for (int q = 0; q < 5; q++)
        #pragma unroll
        for (int p = 0; p < 4; p++) cs[q][p] = 0ull;

    auto ldp = [&](int row, int c, float4& a, float4& b) {
        if (row >= 0 && row < IMG_H && c >= 0 && c + 3 < IMG_W) {
            const size_t idx = (size_t)row * IMG_W + c;
            a = *(const float4*)(p1 + idx);
            b = *(const float4*)(p2 + idx);
        } else {
            a = make_float4(0.f, 0.f, 0.f, 0.f);
            b = make_float4(0.f, 0.f, 0.f, 0.f);
        }
    };

    auto upd_pair = [&](int pi, u64 an, u64 bn, u64 ao, u64 bo) {
        u64 aon = f2mul(ao, (u64)NEG1PK);
        u64 bon = f2mul(bo, (u64)NEG1PK);
        cs[0][pi] = f2add(f2add(cs[0][pi], an), aon);
        cs[1][pi] = f2add(f2add(cs[1][pi], bn), bon);
        cs[2][pi] = f2fma(aon, ao, f2fma(an, an, cs[2][pi]));
        cs[3][pi] = f2fma(bon, bo, f2fma(bn, bn, cs[3][pi]));
        cs[4][pi] = f2fma(aon, bo, f2fma(an, bn, cs[4][pi]));
    };

    auto update = [&](int rn, int ro) {
        #pragma unroll
        for (int g = 0; g < 2; g++) {
            float4 anv, bnv, aov, bov;
            ldp(rn, j + 4 * g, anv, bnv);
            ldp(ro, j + 4 * g, aov, bov);
            upd_pair(2 * g + 0, pk(anv.x, anv.y), pk(bnv.x, bnv.y),
                                pk(aov.x, aov.y), pk(bov.x, bov.y));
            upd_pair(2 * g + 1, pk(anv.z, anv.w), pk(bnv.z, bnv.w),
                                pk(aov.z, aov.w), pk(bov.z, bov.w));
        }
    };

    // rescaled SSIM constants: multiply num & den by 121^4 (exact ratio)
    const u64 K1P  = pk(1.4641f, 1.4641f);     // C1 * 121^2
    const u64 K2P  = pk(13.1769f, 13.1769f);   // C2 * 121^2
    const u64 TWO  = pk(2.f, 2.f);
    const u64 NTWO = pk(-2.f, -2.f);
    const u64 C242 = pk(242.f, 242.f);
    const u64 C121 = pk(121.f, 121.f);

    // ---- prologue: rows y0-5 .. y0+4 (no subtraction) ----
    #pragma unroll 1
    for (int r = 0; r < 10; r++) update(y0 - PADR + r, -10000);

    double acc = 0.0;

    // ---- main loop ----
    #pragma unroll 1
    for (int i = 0; i < YCHUNK; i++) {
        const int oy = y0 + i;
        // window grows 10->11 at i==0 (row oy-6 was never added)
        update(oy + PADR, (i == 0) ? -10000 : (oy - PADR - 1));

        // horizontal 11-col window sums W[q][0..7] for outputs at cols j..j+7
        float W[5][8];
        #pragma unroll
        for (int q = 0; q < 5; q++) {
            float c0, c1, c2, c3, c4, c5, c6, c7;
            upk(cs[q][0], c0, c1); upk(cs[q][1], c2, c3);
            upk(cs[q][2], c4, c5); upk(cs[q][3], c6, c7);

            u64  Lp2 = __shfl_up_sync(FULL, cs[q][2], 1);   // cols j-4, j-3
            u64  Lp3 = __shfl_up_sync(FULL, cs[q][3], 1);   // cols j-2, j-1
            float l5 = __shfl_up_sync(FULL, c3, 1);         // col  j-5
            u64  Rp0 = __shfl_down_sync(FULL, cs[q][0], 1); // cols j+8, j+9
            u64  Rp1 = __shfl_down_sync(FULL, cs[q][1], 1); // cols j+10, j+11
            float r12 = __shfl_down_sync(FULL, c4, 1);      // col  j+12

            float L1v, L2v, L3v, L4v, R0v, R1v, R2v, R3v;
            upk(Lp2, L1v, L2v);
            upk(Lp3, L3v, L4v);
            upk(Rp0, R0v, R1v);
            upk(Rp1, R2v, R3v);

            u64 t = f2add(f2add(Lp2, Lp3), f2add(cs[q][0], cs[q][1]));
            float t0, t1; upk(t, t0, t1);
            const float base8 = t0 + t1;            // cols j-4 .. j+3

            W[q][0] = base8 + l5 + c4 + c5;         // j-5 .. j+5
            W[q][1] = W[q][0] - l5  + c6;
            W[q][2] = W[q][1] - L1v + c7;
            W[q][3] = W[q][2] - L2v + R0v;
            W[q][4] = W[q][3] - L3v + R1v;
            W[q][5] = W[q][4] - L4v + R2v;
            W[q][6] = W[q][5] - c0  + R3v;
            W[q][7] = W[q][6] - c1  + r12;
        }

        float rsum = 0.f;
        #pragma unroll
        for (int k = 0; k < 4; k++) {
            u64 s1  = pk(W[0][2*k], W[0][2*k+1]);
            u64 s2  = pk(W[1][2*k], W[1][2*k+1]);
            u64 s11 = pk(W[2][2*k], W[2][2*k+1]);
            u64 s22 = pk(W[3][2*k], W[3][2*k+1]);
            u64 s12 = pk(W[4][2*k], W[4][2*k+1]);

            u64 P   = f2mul(s1, s2);
            u64 A   = f2fma(P, TWO, K1P);                       // 2*S1S2 + K1
            u64 B   = f2fma(s12, C242, f2fma(P, NTWO, K2P));    // 242*S12 - 2*S1S2 + K2
            u64 num = f2mul(A, B);
            u64 Q   = f2fma(s2, s2, f2mul(s1, s1));             // S1^2 + S2^2
            u64 Cc  = f2add(Q, K1P);
            u64 D   = f2fma(f2add(s11, s22), C121,
                            f2fma(Q, (u64)NEG1PK, K2P));        // 121*(S11+S22) - Q + K2
            u64 den = f2mul(Cc, D);

            float n0, n1, d0, d1;
            upk(num, n0, n1); upk(den, d0, d1);
            if (prod) {
                const int col = j + 2 * k;
                if (col < IMG_W)     rsum += __fdividef(n0, d0);
                if (col + 1 < IMG_W) rsum += __fdividef(n1, d1);
            }
        }
        acc += (double)rsum;
    }

    // ---- warp reduce + one atomic per warp ----
    #pragma unroll
    for (int off = 16; off > 0; off >>= 1)
        acc += __shfl_down_sync(FULL, acc, off);
    if (lane == 0) atomicAdd(&g_accum, acc);
}

extern "C" void kernel_launch(void* const* d_in, const int* in_sizes, int n_in,
                              void* d_out, int out_size) {
    const float* img1 = (const float*)d_in[0];
    const float* img2 = (const float*)d_in[1];
    (void)in_sizes; (void)n_in; (void)out_size;

    zero_acc_kernel<<<1, 1>>>();
    dim3 grid(NSTRIPS, NYCH, BATCH);   // (5, 16, 32) = 2560 single-warp blocks
    ssim_kernel<<<grid, 32>>>(img1, img2);
    finalize_kernel<<<1, 1>>>((float*)d_out);
}